// round 1
// baseline (speedup 1.0000x reference)
#include <cuda_runtime.h>

// Reference constants (np.float32 repr — round-trips bit-exactly).
// Step arrays from the reference's SIGMOID_H / SIGMOID_D / SIGMOID_T.
__device__ constexpr float cH[16] = {
    -0.00443981f, 0.0244156f, -0.01410327f, 0.01784681f,
    -0.00239246f, 0.06331808f, 0.01457577f, 0.01753613f,
     0.01339214f, -0.0131252f, 0.02026613f, 0.00109124f,
    -0.01996419f, 0.00723148f, 0.03052537f, -0.00465259f};
__device__ constexpr float cD[16] = {
    -0.04305673f, 2.0701091e-05f, -0.028386816f, 0.065610707f,
     0.071529418f, -0.0010542608f, 0.0012044241f, 0.00077212957f,
    -0.00072495628f, 0.0010990113f, 0.00087419833f, -0.0031887756f,
    -0.019837018f, 0.00030188679f, 0.00022616754f, -0.0017746047f};
__device__ constexpr float cT[16] = {
    -0.1190194f, 0.03273299f, -0.05586114f, 0.07758415f,
    -0.06072911f, 0.04350465f, -0.06501344f, -0.07967568f,
    -0.08437239f, -0.07040057f, -0.07470815f, 0.01298669f,
     0.12695177f, 0.00617064f, -0.08909994f, 0.05016604f};

// Per-element trajectory. Exact-semantics equivalences used:
//  * z = ((v-T)/(|v|+1) > 0)  <=>  z = (v > T)   (denominator strictly positive)
//  * step 0: v = |x| >= 0 > T[0] = -0.119..., so z fires unconditionally:
//      out starts at D[0]; step 1's "v -= h[1]" is unconditional.
//  * sign(x): +out for x>0, -out for x<0, 0 for x==±0 (matches jnp.sign).
__device__ __forceinline__ float snn_elem(float x) {
    float v = fabsf(x);
    // --- folded step 0 + unconditional part of step 1 ---
    float out = cD[0];
    v -= cH[1];
    bool z = v > cT[1];
    if (z) out += cD[1];
    // --- steps 2..15, predicated, fully unrolled with immediate constants ---
#pragma unroll
    for (int t = 2; t < 16; ++t) {
        if (z) v -= cH[t];
        z = v > cT[t];
        if (z) out += cD[t];
    }
    // --- sign application ---
    float r = (x > 0.0f) ? out : -out;
    return (x == 0.0f) ? 0.0f : r;
}

__global__ void __launch_bounds__(256) snn_vec4_kernel(
    const float4* __restrict__ x, float4* __restrict__ o, int nvec) {
    int i = blockIdx.x * blockDim.x + threadIdx.x;
    if (i < nvec) {
        float4 a = x[i];
        float4 r;
        r.x = snn_elem(a.x);
        r.y = snn_elem(a.y);
        r.z = snn_elem(a.z);
        r.w = snn_elem(a.w);
        o[i] = r;
    }
}

__global__ void snn_tail_kernel(const float* __restrict__ x,
                                float* __restrict__ o,
                                int base, int n) {
    int i = base + blockIdx.x * blockDim.x + threadIdx.x;
    if (i < n) o[i] = snn_elem(x[i]);
}

extern "C" void kernel_launch(void* const* d_in, const int* in_sizes, int n_in,
                              void* d_out, int out_size) {
    const float* x = (const float*)d_in[0];
    float* out = (float*)d_out;
    int n = in_sizes[0];

    int nvec = n >> 2;
    if (nvec > 0) {
        int threads = 256;
        int blocks = (nvec + threads - 1) / threads;
        snn_vec4_kernel<<<blocks, threads>>>(
            (const float4*)x, (float4*)out, nvec);
    }
    int rem = n & 3;
    if (rem > 0) {
        snn_tail_kernel<<<1, 32>>>(x, out, nvec << 2, n);
    }
}